// round 1
// baseline (speedup 1.0000x reference)
#include <cuda_runtime.h>
#include <math.h>

#define NQ 16384
#define NC 8192
#define DD 256
#define TK 16
#define ZELEMS 4194304
#define LOSS_OFF 4194304
#define PERP_OFF 4194305
#define UNIQ_OFF 4194306
#define IDX_OFF  4194307

// device scratch (no allocs allowed)
__device__ float  g_wT[DD * NC];      // weight transposed: [k][c]  (8 MB)
__device__ float  g_cnorm[NC];        // ||w_c||^2
__device__ int    g_counts[NC];
__device__ int    g_idx[NQ];
__device__ float  g_lpart[16384];     // per-block loss partials

// ---------------- prep kernels ----------------

__global__ void k_zero() {
    int t = blockIdx.x * blockDim.x + threadIdx.x;
    if (t < NC) g_counts[t] = 0;
}

__global__ void k_transpose(const float* __restrict__ w) {
    __shared__ float tile[32][33];
    int c0 = blockIdx.x * 32, k0 = blockIdx.y * 32;
    int tx = threadIdx.x, ty = threadIdx.y;
#pragma unroll
    for (int r = 0; r < 4; r++)
        tile[ty + r * 8][tx] = w[(c0 + ty + r * 8) * DD + k0 + tx];
    __syncthreads();
#pragma unroll
    for (int r = 0; r < 4; r++)
        g_wT[(k0 + ty + r * 8) * NC + c0 + tx] = tile[tx][ty + r * 8];
}

__global__ void k_cnorm(const float* __restrict__ w) {
    int warp = threadIdx.x >> 5, lane = threadIdx.x & 31;
    int c = blockIdx.x * 8 + warp;
    const float* row = w + c * DD;
    float s = 0.f;
#pragma unroll
    for (int j = 0; j < 8; j++) { float v = row[lane + j * 32]; s += v * v; }
#pragma unroll
    for (int off = 16; off; off >>= 1) s += __shfl_xor_sync(0xffffffffu, s, off);
    if (lane == 0) g_cnorm[c] = s;
}

// ---------------- argmin GEMM ----------------

__device__ __forceinline__ void ffma2(unsigned long long& acc,
                                      unsigned long long a, unsigned long long b) {
    asm("fma.rn.f32x2 %0, %1, %2, %0;" : "+l"(acc) : "l"(a), "l"(b));
}
__device__ __forceinline__ float f2lo(unsigned long long v) {
    return __uint_as_float((unsigned)(v & 0xffffffffu));
}
__device__ __forceinline__ float f2hi(unsigned long long v) {
    return __uint_as_float((unsigned)(v >> 32));
}

// grid = 128 CTAs (one 128-query tile each), 256 threads.
// Q tile loaded straight from z (layout b,c,l,h,w: for fixed k=channel, the 128
// spatial positions are contiguous -> coalesced, no query-transpose pass needed).
__global__ void __launch_bounds__(256, 1) k_argmin(const float* __restrict__ z) {
    __shared__ float2 Qs[2][TK][128];   // duplicated query values (f32x2 ready)
    __shared__ float4 Cs[2][TK][32];    // 128 code values per k row

    int t = threadIdx.x;
    int tx = t & 15, ty = t >> 4;
    int qt = blockIdx.x;
    const float* zq = z + ((qt >> 5) * 1048576 + (qt & 31) * 128);

    int e0 = t, e1 = t + 256;
    int k0e = e0 >> 5, q0e = e0 & 31;
    int k1e = e1 >> 5, q1e = e1 & 31;

    unsigned long long acc[8][4];
#pragma unroll
    for (int i = 0; i < 8; i++)
#pragma unroll
        for (int j = 0; j < 4; j++) acc[i][j] = 0ULL;

    float bs[8];
    int   bi[8];
#pragma unroll
    for (int i = 0; i < 8; i++) { bs[i] = __int_as_float(0x7f800000); bi[i] = 0; }

    float4 pq0, pq1, pc0, pc1;
    // prefetch chunk m=0
    pq0 = *(const float4*)(zq + k0e * 4096 + q0e * 4);
    pq1 = *(const float4*)(zq + k1e * 4096 + q1e * 4);
    pc0 = *(const float4*)(g_wT + k0e * NC + q0e * 4);
    pc1 = *(const float4*)(g_wT + k1e * NC + q1e * 4);

    int buf = 0;
    {
        float4* qd0 = (float4*)&Qs[buf][k0e][q0e * 4];
        qd0[0] = make_float4(pq0.x, pq0.x, pq0.y, pq0.y);
        qd0[1] = make_float4(pq0.z, pq0.z, pq0.w, pq0.w);
        float4* qd1 = (float4*)&Qs[buf][k1e][q1e * 4];
        qd1[0] = make_float4(pq1.x, pq1.x, pq1.y, pq1.y);
        qd1[1] = make_float4(pq1.z, pq1.z, pq1.w, pq1.w);
        Cs[buf][k0e][q0e] = pc0;
        Cs[buf][k1e][q1e] = pc1;
    }
    __syncthreads();

    int ty4 = ty * 4, tx2 = tx * 2;

    for (int m = 0; m < 1024; m++) {            // 64 code tiles * 16 k-chunks
        if (m + 1 < 1024) {
            int mn = m + 1;
            int k0 = (mn & 15) * 16;
            int c0 = (mn >> 4) * 128;
            pq0 = *(const float4*)(zq + (k0 + k0e) * 4096 + q0e * 4);
            pq1 = *(const float4*)(zq + (k0 + k1e) * 4096 + q1e * 4);
            pc0 = *(const float4*)(g_wT + (k0 + k0e) * NC + c0 + q0e * 4);
            pc1 = *(const float4*)(g_wT + (k0 + k1e) * NC + c0 + q1e * 4);
        }
#pragma unroll
        for (int kk = 0; kk < TK; kk++) {
            const unsigned long long* qrow = (const unsigned long long*)Qs[buf][kk];
            const unsigned long long* crow = (const unsigned long long*)Cs[buf][kk];
            unsigned long long qa[8], cp[4];
#pragma unroll
            for (int i = 0; i < 4; i++) { qa[i] = qrow[ty4 + i]; qa[4 + i] = qrow[64 + ty4 + i]; }
            cp[0] = crow[tx2]; cp[1] = crow[tx2 + 1];
            cp[2] = crow[32 + tx2]; cp[3] = crow[33 + tx2];
#pragma unroll
            for (int i = 0; i < 8; i++)
#pragma unroll
                for (int j = 0; j < 4; j++)
                    ffma2(acc[i][j], qa[i], cp[j]);
        }
        if ((m & 15) == 15) {                   // tile finished: score & reset
            int cb = (m >> 4) * 128;
            float4 cn0 = *(const float4*)(g_cnorm + cb + tx * 4);
            float4 cn1 = *(const float4*)(g_cnorm + cb + 64 + tx * 4);
            int cA = cb + tx * 4, cB = cb + 64 + tx * 4;
#pragma unroll
            for (int i = 0; i < 8; i++) {
                float sc[8];
                sc[0] = cn0.x - 2.f * f2lo(acc[i][0]);
                sc[1] = cn0.y - 2.f * f2hi(acc[i][0]);
                sc[2] = cn0.z - 2.f * f2lo(acc[i][1]);
                sc[3] = cn0.w - 2.f * f2hi(acc[i][1]);
                sc[4] = cn1.x - 2.f * f2lo(acc[i][2]);
                sc[5] = cn1.y - 2.f * f2hi(acc[i][2]);
                sc[6] = cn1.z - 2.f * f2lo(acc[i][3]);
                sc[7] = cn1.w - 2.f * f2hi(acc[i][3]);
#pragma unroll
                for (int u = 0; u < 8; u++) {
                    int cu = (u < 4) ? (cA + u) : (cB + u - 4);
                    if (sc[u] < bs[i] || (sc[u] == bs[i] && cu < bi[i])) {
                        bs[i] = sc[u]; bi[i] = cu;
                    }
                }
#pragma unroll
                for (int j = 0; j < 4; j++) acc[i][j] = 0ULL;
            }
        }
        if (m + 1 < 1024) {
            int nb = buf ^ 1;
            float4* qd0 = (float4*)&Qs[nb][k0e][q0e * 4];
            qd0[0] = make_float4(pq0.x, pq0.x, pq0.y, pq0.y);
            qd0[1] = make_float4(pq0.z, pq0.z, pq0.w, pq0.w);
            float4* qd1 = (float4*)&Qs[nb][k1e][q1e * 4];
            qd1[0] = make_float4(pq1.x, pq1.x, pq1.y, pq1.y);
            qd1[1] = make_float4(pq1.z, pq1.z, pq1.w, pq1.w);
            Cs[nb][k0e][q0e] = pc0;
            Cs[nb][k1e][q1e] = pc1;
            __syncthreads();
            buf ^= 1;
        }
    }

    // cross-lane (16 lanes sharing ty) argmin reduce; tie-break = lowest index
#pragma unroll
    for (int i = 0; i < 8; i++) {
        float s = bs[i]; int ci = bi[i];
#pragma unroll
        for (int off = 8; off; off >>= 1) {
            float so = __shfl_xor_sync(0xffffffffu, s, off);
            int   co = __shfl_xor_sync(0xffffffffu, ci, off);
            if (so < s || (so == s && co < ci)) { s = so; ci = co; }
        }
        if (tx == 0) {
            int q = qt * 128 + ((i < 4) ? (ty * 4 + i) : (64 + ty * 4 + (i - 4)));
            g_idx[q] = ci;
            atomicAdd(&g_counts[ci], 1);
        }
    }
}

// ---------------- gather + straight-through + loss partials ----------------

__global__ void k_gather(const float* __restrict__ z, const float* __restrict__ w,
                         float* __restrict__ out) {
    int o = blockIdx.x * 256 + threadIdx.x;    // output element (b,c,l,h,w order)
    int s = o & 4095;
    int c = (o >> 12) & 255;
    int b = o >> 20;
    int n = b * 4096 + s;
    int id = g_idx[n];
    float zv = z[o];
    float wv = __ldg(w + id * DD + c);
    float d  = wv - zv;                         // matches (z_q - zc) rounding
    out[o] = zv + d;                            // straight-through value

    float v = d * d;
#pragma unroll
    for (int off = 16; off; off >>= 1) v += __shfl_xor_sync(0xffffffffu, v, off);
    __shared__ float red[8];
    if ((threadIdx.x & 31) == 0) red[threadIdx.x >> 5] = v;
    __syncthreads();
    if (threadIdx.x == 0) {
        float tsum = 0.f;
#pragma unroll
        for (int i = 0; i < 8; i++) tsum += red[i];
        g_lpart[blockIdx.x] = tsum;
    }
}

__global__ void k_idxout(float* __restrict__ out) {
    int t = blockIdx.x * blockDim.x + threadIdx.x;
    if (t < NQ) out[IDX_OFF + t] = (float)g_idx[t];
}

// ---------------- finalize: loss, perplexity, unique ----------------

__global__ void k_final(float* __restrict__ out) {
    __shared__ double ds[32];
    __shared__ float  es[32];
    __shared__ int    us[32];
    int t = threadIdx.x, lane = t & 31, warp = t >> 5;

    double lsum = 0.0;
    for (int i = t; i < 16384; i += 1024) lsum += (double)g_lpart[i];

    float ent = 0.f; int uniq = 0;
    for (int c = t; c < NC; c += 1024) {
        int cnt = g_counts[c];
        float p = (float)cnt * (1.0f / 16384.0f);
        ent += p * logf(p + 1e-10f);
        uniq += (cnt > 0);
    }
#pragma unroll
    for (int off = 16; off; off >>= 1) {
        lsum += __shfl_xor_sync(0xffffffffu, lsum, off);
        ent  += __shfl_xor_sync(0xffffffffu, ent, off);
        uniq += __shfl_xor_sync(0xffffffffu, uniq, off);
    }
    if (lane == 0) { ds[warp] = lsum; es[warp] = ent; us[warp] = uniq; }
    __syncthreads();
    if (t == 0) {
        double L = 0.0; float E = 0.f; int U = 0;
        for (int i = 0; i < 32; i++) { L += ds[i]; E += es[i]; U += us[i]; }
        out[LOSS_OFF] = 0.25f * (float)(L * (1.0 / 4194304.0));
        out[PERP_OFF] = expf(-E);
        out[UNIQ_OFF] = (float)U;
    }
}

// ---------------- launch ----------------

extern "C" void kernel_launch(void* const* d_in, const int* in_sizes, int n_in,
                              void* d_out, int out_size) {
    const float* z = (const float*)d_in[0];   // [4,256,16,16,16]
    const float* w = (const float*)d_in[1];   // [8192,256]
    float* out = (float*)d_out;

    k_zero<<<8, 1024>>>();
    k_transpose<<<dim3(NC / 32, DD / 32), dim3(32, 8)>>>(w);
    k_cnorm<<<NC / 8, 256>>>(w);
    k_argmin<<<NQ / 128, 256>>>(z);
    k_gather<<<ZELEMS / 256, 256>>>(z, w, out);
    k_idxout<<<16, 1024>>>(out);
    k_final<<<1, 1024>>>(out);
}

// round 3
// speedup vs baseline: 1.1789x; 1.1789x over previous
#include <cuda_runtime.h>
#include <cuda_bf16.h>
#include <math.h>
#include <stdint.h>

#define NQ 16384
#define NC 8192
#define DD 256
#define ZELEMS 4194304
#define LOSS_OFF 4194304
#define PERP_OFF 4194305
#define UNIQ_OFF 4194306
#define IDX_OFF  4194307

// ---------------- device scratch (no allocs allowed) ----------------
__device__ float          g_cnorm[NC];
__device__ int            g_counts[NC];
__device__ int            g_idx[NQ];
__device__ float          g_lpart[16384];
__device__ __nv_bfloat16  g_wB[NC * DD];     // bf16 codebook [code][k]
__device__ float          g_zT[NQ * DD];     // channel-last queries
__device__ float          g_bm8[1024 * NQ];  // per-8-code bin minima, bin-major

// ---------------- PTX helpers (sm_80-era, family-wide) ----------------
__device__ __forceinline__ uint32_t s2u(const void* p) {
    uint32_t a;
    asm("{ .reg .u64 t; cvta.to.shared.u64 t, %1; cvt.u32.u64 %0, t; }" : "=r"(a) : "l"(p));
    return a;
}
__device__ __forceinline__ void ldsm4(uint32_t addr, uint32_t& r0, uint32_t& r1,
                                      uint32_t& r2, uint32_t& r3) {
    asm volatile("ldmatrix.sync.aligned.m8n8.x4.shared.b16 {%0,%1,%2,%3}, [%4];"
                 : "=r"(r0), "=r"(r1), "=r"(r2), "=r"(r3) : "r"(addr));
}
__device__ __forceinline__ void mma16816(float* d, const uint32_t* a, uint32_t b0, uint32_t b1) {
    asm volatile(
        "mma.sync.aligned.m16n8k16.row.col.f32.bf16.bf16.f32 "
        "{%0,%1,%2,%3},{%4,%5,%6,%7},{%8,%9},{%0,%1,%2,%3};"
        : "+f"(d[0]), "+f"(d[1]), "+f"(d[2]), "+f"(d[3])
        : "r"(a[0]), "r"(a[1]), "r"(a[2]), "r"(a[3]), "r"(b0), "r"(b1));
}
#define CPASYNC(dst, src) \
    asm volatile("cp.async.cg.shared.global [%0], [%1], 16;" :: "r"(dst), "l"(src))
#define CPCOMMIT() asm volatile("cp.async.commit_group;")
#define CPWAIT(n)  asm volatile("cp.async.wait_group %0;" :: "n"(n))

// smem layout: A 64K | B0 64K | B1 64K | cn 32K
#define SM_A  0
#define SM_B0 65536
#define SM_B1 131072
#define SM_CN 196608
#define SMEM_SZ 229376

// ---------------- prep kernels ----------------
__global__ void k_zero() {
    int t = blockIdx.x * blockDim.x + threadIdx.x;
    if (t < NC) g_counts[t] = 0;
}

__global__ void k_cnorm(const float* __restrict__ w) {
    int warp = threadIdx.x >> 5, lane = threadIdx.x & 31;
    int c = blockIdx.x * 8 + warp;
    const float* row = w + c * DD;
    float s = 0.f;
#pragma unroll
    for (int j = 0; j < 8; j++) { float v = row[lane + j * 32]; s += v * v; }
#pragma unroll
    for (int off = 16; off; off >>= 1) s += __shfl_xor_sync(0xffffffffu, s, off);
    if (lane == 0) g_cnorm[c] = s;
}

__global__ void k_wbf16(const float* __restrict__ w) {
    int t = blockIdx.x * 256 + threadIdx.x;
    g_wB[t] = __float2bfloat16(w[t]);
}

__global__ void k_zt(const float* __restrict__ z) {
    __shared__ float tile[32][33];
    int s0 = blockIdx.x * 32, c0 = blockIdx.y * 32, b = blockIdx.z;
    int tx = threadIdx.x, ty = threadIdx.y;
#pragma unroll
    for (int r = 0; r < 4; r++)
        tile[ty + r * 8][tx] = z[b * 1048576 + (c0 + ty + r * 8) * 4096 + s0 + tx];
    __syncthreads();
#pragma unroll
    for (int r = 0; r < 4; r++)
        g_zT[(b * 4096 + s0 + ty + r * 8) * DD + c0 + tx] = tile[tx][ty + r * 8];
}

// ---------------- HMMA distance GEMM + per-8-code bin minima ----------------
// grid = 128 CTAs (one 128-query slab), 256 thr; loops 64 code tiles of 128.
__global__ void __launch_bounds__(256, 1) k_tc(const float* __restrict__ z) {
    extern __shared__ char smem[];
    uint32_t sb = s2u(smem);
    float* cn_s = (float*)(smem + SM_CN);

    int tid = threadIdx.x, lane = tid & 31, wid = tid >> 5;
    int qbase = blockIdx.x * 128;
    int b = blockIdx.x >> 5, s0 = (blockIdx.x & 31) * 128;
    const float* zb = z + b * 1048576 + s0;

    // prefetch B tile 0 via cp.async (overlaps with A/cn fill)
    {
        const char* gs = (const char*)g_wB;   // tile 0
#pragma unroll
        for (int i = 0; i < 16; i++) {
            int e = tid + i * 256;
            int n = e >> 5, kc = e & 31;
            CPASYNC(sb + SM_B0 + n * 512 + ((kc ^ (n & 7)) << 4), gs + n * 512 + kc * 16);
        }
        CPCOMMIT();
    }

    // cn -> smem
    {
        const float4* src = (const float4*)g_cnorm;
        float4* dst = (float4*)cn_s;
        for (int i = tid; i < 2048; i += 256) dst[i] = src[i];
    }
    // A fill: 128 q x 256 k bf16, ldmatrix swizzle (chunk ^ (row&7))
    for (int e = tid; e < 8192; e += 256) {
        int c = e >> 5, r4 = (e & 31) * 4;
        float4 v = *(const float4*)(zb + c * 4096 + r4);
        int kc = c >> 3, ko = (c & 7) * 2;
        float vv[4] = {v.x, v.y, v.z, v.w};
#pragma unroll
        for (int j = 0; j < 4; j++) {
            int row = r4 + j;
            *(__nv_bfloat16*)(smem + SM_A + row * 512 + ((kc ^ (row & 7)) << 4) + ko) =
                __float2bfloat16(vv[j]);
        }
    }
    __syncthreads();

    int wm = (wid & 3) * 32, wn = (wid >> 2) * 64;
    int aRow = wm + (lane & 15);
    int aSw = lane & 7;
    int aKo = lane >> 4;                       // +1 chunk for upper half-warp
    int bN = wn + (lane & 7) + ((lane >> 4) << 3);
    int bKo = (lane >> 3) & 1;

    for (int t = 0; t < 64; t++) {
        if (t + 1 < 64) {
            const char* gs = (const char*)g_wB + (size_t)(t + 1) * 65536;
            uint32_t bb = sb + (((t + 1) & 1) ? SM_B1 : SM_B0);
#pragma unroll
            for (int i = 0; i < 16; i++) {
                int e = tid + i * 256;
                int n = e >> 5, kc = e & 31;
                CPASYNC(bb + n * 512 + ((kc ^ (n & 7)) << 4), gs + n * 512 + kc * 16);
            }
            CPCOMMIT();
            CPWAIT(1);
        } else {
            CPWAIT(0);
        }
        __syncthreads();

        uint32_t sB = sb + ((t & 1) ? SM_B1 : SM_B0);
        float d[2][8][4];
#pragma unroll
        for (int mi = 0; mi < 2; mi++)
#pragma unroll
            for (int ni = 0; ni < 8; ni++)
#pragma unroll
                for (int u = 0; u < 4; u++) d[mi][ni][u] = 0.f;

#pragma unroll 4
        for (int ks = 0; ks < 16; ks++) {
            int kkA = 2 * ks + aKo;
            uint32_t a0[4], a1[4];
            ldsm4(sb + SM_A + aRow * 512 + ((kkA ^ aSw) << 4), a0[0], a0[1], a0[2], a0[3]);
            ldsm4(sb + SM_A + (aRow + 16) * 512 + ((kkA ^ aSw) << 4), a1[0], a1[1], a1[2], a1[3]);
            int kkB = 2 * ks + bKo;
#pragma unroll
            for (int nb = 0; nb < 4; nb++) {
                int n = bN + nb * 16;
                uint32_t b0, b1, b2, b3;
                ldsm4(sB + n * 512 + ((kkB ^ (lane & 7)) << 4), b0, b1, b2, b3);
                mma16816(d[0][nb * 2], a0, b0, b1);
                mma16816(d[0][nb * 2 + 1], a0, b2, b3);
                mma16816(d[1][nb * 2], a1, b0, b1);
                mma16816(d[1][nb * 2 + 1], a1, b2, b3);
            }
        }

        // epilogue: dist = cn - 2*dot; per-8-col bin min; lanes %4==0 write
#pragma unroll
        for (int mi = 0; mi < 2; mi++) {
#pragma unroll
            for (int ni = 0; ni < 8; ni++) {
                float2 cn2 = *(float2*)&cn_s[t * 128 + wn + ni * 8 + (lane & 3) * 2];
                float v0 = fminf(cn2.x - 2.f * d[mi][ni][0], cn2.y - 2.f * d[mi][ni][1]);
                float v1 = fminf(cn2.x - 2.f * d[mi][ni][2], cn2.y - 2.f * d[mi][ni][3]);
                v0 = fminf(v0, __shfl_xor_sync(0xffffffffu, v0, 1));
                v0 = fminf(v0, __shfl_xor_sync(0xffffffffu, v0, 2));
                v1 = fminf(v1, __shfl_xor_sync(0xffffffffu, v1, 1));
                v1 = fminf(v1, __shfl_xor_sync(0xffffffffu, v1, 2));
                if ((lane & 3) == 0) {
                    int bin = t * 16 + (wn >> 3) + ni;
                    int q0 = qbase + wm + mi * 16 + (lane >> 2);
                    g_bm8[(size_t)bin * NQ + q0] = v0;
                    g_bm8[(size_t)bin * NQ + q0 + 8] = v1;
                }
            }
        }
        __syncthreads();
    }
}

// ---------------- exact rescore of candidate bins ----------------
__global__ void k_rescore(const float* __restrict__ w) {
    int q = blockIdx.x * 128 + threadIdx.x;
    float m = __int_as_float(0x7f800000);
#pragma unroll 8
    for (int i = 0; i < 1024; i++) m = fminf(m, g_bm8[(size_t)i * NQ + q]);
    float thr = m + 2.0f;   // covers bf16 approx error with huge margin

    float best = __int_as_float(0x7f800000);
    int bi = 0;
    const float4* zq4 = (const float4*)(g_zT + (size_t)q * DD);
    for (int i = 0; i < 1024; i++) {
        if (g_bm8[(size_t)i * NQ + q] <= thr) {
            float acc[8];
#pragma unroll
            for (int k = 0; k < 8; k++) acc[k] = 0.f;
            const float4* wr = (const float4*)(w + (size_t)i * 8 * DD);
            for (int c4 = 0; c4 < 64; c4++) {
                float4 zv = __ldg(&zq4[c4]);
#pragma unroll
                for (int k = 0; k < 8; k++) {
                    float4 wv = __ldg(&wr[k * 64 + c4]);
                    acc[k] = fmaf(zv.x, wv.x, acc[k]);
                    acc[k] = fmaf(zv.y, wv.y, acc[k]);
                    acc[k] = fmaf(zv.z, wv.z, acc[k]);
                    acc[k] = fmaf(zv.w, wv.w, acc[k]);
                }
            }
#pragma unroll
            for (int k = 0; k < 8; k++) {
                int c = i * 8 + k;
                float sc = g_cnorm[c] - 2.f * acc[k];
                if (sc < best) { best = sc; bi = c; }
            }
        }
    }
    g_idx[q] = bi;
    atomicAdd(&g_counts[bi], 1);
}

// ---------------- gather + straight-through + loss partials ----------------
__global__ void k_gather(const float* __restrict__ z, const float* __restrict__ w,
                         float* __restrict__ out) {
    int o = blockIdx.x * 256 + threadIdx.x;
    int s = o & 4095;
    int c = (o >> 12) & 255;
    int b = o >> 20;
    int n = b * 4096 + s;
    int id = g_idx[n];
    float zv = z[o];
    float wv = __ldg(w + id * DD + c);
    float d = wv - zv;
    out[o] = zv + d;

    float v = d * d;
#pragma unroll
    for (int off = 16; off; off >>= 1) v += __shfl_xor_sync(0xffffffffu, v, off);
    __shared__ float red[8];
    if ((threadIdx.x & 31) == 0) red[threadIdx.x >> 5] = v;
    __syncthreads();
    if (threadIdx.x == 0) {
        float tsum = 0.f;
#pragma unroll
        for (int i = 0; i < 8; i++) tsum += red[i];
        g_lpart[blockIdx.x] = tsum;
    }
}

__global__ void k_idxout(float* __restrict__ out) {
    int t = blockIdx.x * blockDim.x + threadIdx.x;
    if (t < NQ) out[IDX_OFF + t] = (float)g_idx[t];
}

__global__ void k_final(float* __restrict__ out) {
    __shared__ double ds[32];
    __shared__ float es[32];
    __shared__ int us[32];
    int t = threadIdx.x, lane = t & 31, warp = t >> 5;

    double lsum = 0.0;
    for (int i = t; i < 16384; i += 1024) lsum += (double)g_lpart[i];

    float ent = 0.f; int uniq = 0;
    for (int c = t; c < NC; c += 1024) {
        int cnt = g_counts[c];
        float p = (float)cnt * (1.0f / 16384.0f);
        ent += p * logf(p + 1e-10f);
        uniq += (cnt > 0);
    }
#pragma unroll
    for (int off = 16; off; off >>= 1) {
        lsum += __shfl_xor_sync(0xffffffffu, lsum, off);
        ent += __shfl_xor_sync(0xffffffffu, ent, off);
        uniq += __shfl_xor_sync(0xffffffffu, uniq, off);
    }
    if (lane == 0) { ds[warp] = lsum; es[warp] = ent; us[warp] = uniq; }
    __syncthreads();
    if (t == 0) {
        double L = 0.0; float E = 0.f; int U = 0;
        for (int i = 0; i < 32; i++) { L += ds[i]; E += es[i]; U += us[i]; }
        out[LOSS_OFF] = 0.25f * (float)(L * (1.0 / 4194304.0));
        out[PERP_OFF] = expf(-E);
        out[UNIQ_OFF] = (float)U;
    }
}

// ---------------- launch ----------------
extern "C" void kernel_launch(void* const* d_in, const int* in_sizes, int n_in,
                              void* d_out, int out_size) {
    const float* z = (const float*)d_in[0];
    const float* w = (const float*)d_in[1];
    float* out = (float*)d_out;

    cudaFuncSetAttribute(k_tc, cudaFuncAttributeMaxDynamicSharedMemorySize, SMEM_SZ);

    k_zero<<<8, 1024>>>();
    k_cnorm<<<NC / 8, 256>>>(w);
    k_wbf16<<<NC, 256>>>(w);
    k_zt<<<dim3(128, 8, 4), dim3(32, 8)>>>(z);
    k_tc<<<NQ / 128, 256, SMEM_SZ>>>(z);
    k_rescore<<<NQ / 128, 128>>>(w);
    k_gather<<<ZELEMS / 256, 256>>>(z, w, out);
    k_idxout<<<16, 1024>>>(out);
    k_final<<<1, 1024>>>(out);
}